// round 2
// baseline (speedup 1.0000x reference)
#include <cuda_runtime.h>

// Problem constants (fixed by setup_inputs)
#define N_ROWS 131072
#define DIM    32
#define NLAYER 4
#define NE     256
#define BETA   0.25f

// Global loss accumulator (scratch; no allocs allowed)
__device__ double g_loss_acc;

__global__ void rvq_zero_kernel() {
    g_loss_acc = 0.0;
}

__global__ void rvq_finalize_kernel(float* __restrict__ out) {
    // mean over L of (1+beta) * mean((xq - r)^2)
    double scale = (1.0 + (double)BETA) / ((double)NLAYER * (double)N_ROWS * (double)DIM);
    out[(size_t)N_ROWS * DIM] = (float)(g_loss_acc * scale);
}

__global__ __launch_bounds__(128, 4)
void rvq_main_kernel(const float* __restrict__ x,
                     const float* __restrict__ codebooks,
                     float* __restrict__ out)
{
    // dynamic smem: [NE*DIM] codebook + [NE] squared norms
    extern __shared__ float smem[];
    float* sc  = smem;            // NE * DIM
    float* ccn = smem + NE * DIM; // NE

    const int tid = threadIdx.x;
    const size_t row = (size_t)blockIdx.x * blockDim.x + tid;

    // Load this row into registers
    float r[DIM];
    float xq[DIM];
    {
        const float4* xin = (const float4*)(x + row * DIM);
        #pragma unroll
        for (int j = 0; j < DIM / 4; j++) {
            float4 v = xin[j];
            r[4*j+0] = v.x; r[4*j+1] = v.y; r[4*j+2] = v.z; r[4*j+3] = v.w;
            xq[4*j+0] = 0.f; xq[4*j+1] = 0.f; xq[4*j+2] = 0.f; xq[4*j+3] = 0.f;
        }
    }

    int   best_idx[NLAYER];
    float loss_sum = 0.f;

    for (int l = 0; l < NLAYER; l++) {
        __syncthreads();  // protect smem reuse across layers
        // Stage layer-l codebook into shared memory (float4, coalesced)
        {
            const float4* gcb = (const float4*)(codebooks + (size_t)l * NE * DIM);
            float4* sc4 = (float4*)sc;
            #pragma unroll
            for (int i = tid; i < NE * DIM / 4; i += 128) sc4[i] = gcb[i];
        }
        __syncthreads();
        // Per-code squared norms
        for (int e = tid; e < NE; e += 128) {
            const float* c = sc + e * DIM;
            float s = 0.f;
            #pragma unroll
            for (int d = 0; d < DIM; d++) s = fmaf(c[d], c[d], s);
            ccn[e] = s;
        }
        __syncthreads();

        // ||r||^2
        float rr = 0.f;
        #pragma unroll
        for (int d = 0; d < DIM; d++) rr = fmaf(r[d], r[d], rr);

        // Argmin over 256 codes: dist = (rr + ||c||^2) - 2*dot  (matches ref expansion)
        float bd = 3.4e38f;
        int   be = 0;
        #pragma unroll 2
        for (int e = 0; e < NE; e++) {
            const float4* c4 = (const float4*)(sc + e * DIM);
            float a0 = 0.f, a1 = 0.f, a2 = 0.f, a3 = 0.f;
            #pragma unroll
            for (int j = 0; j < DIM / 4; j++) {
                float4 c = c4[j];   // broadcast LDS.128 (all lanes same addr, no conflicts)
                a0 = fmaf(r[4*j+0], c.x, a0);
                a1 = fmaf(r[4*j+1], c.y, a1);
                a2 = fmaf(r[4*j+2], c.z, a2);
                a3 = fmaf(r[4*j+3], c.w, a3);
            }
            float dot  = (a0 + a1) + (a2 + a3);
            float dist = (rr + ccn[e]) - 2.f * dot;
            if (dist < bd) { bd = dist; be = e; }   // strict < == first-min (jnp.argmin)
        }
        best_idx[l] = be;

        // Update: diff = c - r; loss += diff^2; xq += c; r = -(c - r)
        {
            const float4* cb = (const float4*)(sc + be * DIM);
            #pragma unroll
            for (int j = 0; j < DIM / 4; j++) {
                float4 c = cb[j];
                float d0 = c.x - r[4*j+0];
                float d1 = c.y - r[4*j+1];
                float d2 = c.z - r[4*j+2];
                float d3 = c.w - r[4*j+3];
                loss_sum = fmaf(d0, d0, loss_sum);
                loss_sum = fmaf(d1, d1, loss_sum);
                loss_sum = fmaf(d2, d2, loss_sum);
                loss_sum = fmaf(d3, d3, loss_sum);
                xq[4*j+0] += c.x; xq[4*j+1] += c.y;
                xq[4*j+2] += c.z; xq[4*j+3] += c.w;
                r[4*j+0] = -d0; r[4*j+1] = -d1;
                r[4*j+2] = -d2; r[4*j+3] = -d3;
            }
        }
    }

    // Write x_q (16B-aligned: row*128 bytes from base)
    {
        float4* xo = (float4*)(out + row * DIM);
        #pragma unroll
        for (int j = 0; j < DIM / 4; j++)
            xo[j] = make_float4(xq[4*j+0], xq[4*j+1], xq[4*j+2], xq[4*j+3]);
    }
    // Write indices (as float), layout [N, L] after the loss scalar.
    // Base offset is odd (N*D + 1), so the region is only 4B-aligned -> scalar stores.
    {
        float* oi = out + (size_t)N_ROWS * DIM + 1 + row * NLAYER;
        #pragma unroll
        for (int l = 0; l < NLAYER; l++)
            oi[l] = (float)best_idx[l];
    }

    // Block-level loss reduction -> one double atomic per block
    __shared__ float warp_part[4];
    // warp reduce
    #pragma unroll
    for (int off = 16; off > 0; off >>= 1)
        loss_sum += __shfl_down_sync(0xFFFFFFFFu, loss_sum, off);
    int lane = tid & 31, wid = tid >> 5;
    if (lane == 0) warp_part[wid] = loss_sum;
    __syncthreads();
    if (tid == 0) {
        float s = warp_part[0] + warp_part[1] + warp_part[2] + warp_part[3];
        atomicAdd(&g_loss_acc, (double)s);
    }
}

extern "C" void kernel_launch(void* const* d_in, const int* in_sizes, int n_in,
                              void* d_out, int out_size)
{
    const float* x    = (const float*)d_in[0];
    const float* cbs  = (const float*)d_in[1];
    float* out        = (float*)d_out;
    (void)in_sizes; (void)n_in; (void)out_size;

    const int threads = 128;
    const int blocks  = N_ROWS / threads;        // 1024
    const int smem    = NE * DIM * sizeof(float) + NE * sizeof(float); // 33 KB

    rvq_zero_kernel<<<1, 1>>>();
    rvq_main_kernel<<<blocks, threads, smem>>>(x, cbs, out);
    rvq_finalize_kernel<<<1, 1>>>(out);
}

// round 3
// speedup vs baseline: 1.0855x; 1.0855x over previous
#include <cuda_runtime.h>
#include <cstdint>

#define N_ROWS 131072
#define DIM    32
#define NLAYER 4
#define NE     256
#define BETA   0.25f
#define TPB    128
#define NBLK   (N_ROWS / TPB)   // 1024

// Scratch (no allocs allowed): per-block loss partials + completion counter
__device__ double       g_part[NBLK];
__device__ unsigned int g_count = 0;

__device__ __forceinline__ uint64_t pack2(float lo, float hi) {
    uint64_t v;
    asm("mov.b64 %0, {%1, %2};" : "=l"(v) : "f"(lo), "f"(hi));
    return v;
}
__device__ __forceinline__ void fma2(uint64_t& d, uint64_t a, uint64_t b) {
    asm("fma.rn.f32x2 %0, %1, %2, %0;" : "+l"(d) : "l"(a), "l"(b));
}
__device__ __forceinline__ uint64_t add2(uint64_t a, uint64_t b) {
    uint64_t v;
    asm("add.rn.f32x2 %0, %1, %2;" : "=l"(v) : "l"(a), "l"(b));
    return v;
}
__device__ __forceinline__ void unpack2(uint64_t v, float& lo, float& hi) {
    asm("mov.b64 {%0, %1}, %2;" : "=f"(lo), "=f"(hi) : "l"(v));
}

__global__ __launch_bounds__(TPB, 4)
void rvq_main_kernel(const float* __restrict__ x,
                     const float* __restrict__ codebooks,
                     float* __restrict__ out)
{
    // dynamic smem: [NE*DIM] codebook + [NE] squared norms
    extern __shared__ float smem[];
    float* sc  = smem;            // NE * DIM
    float* ccn = smem + NE * DIM; // NE

    const int tid = threadIdx.x;
    const size_t row = (size_t)blockIdx.x * TPB + tid;

    float r[DIM];   // residual (scalar, authoritative)
    float xq[DIM];
    {
        const float4* xin = (const float4*)(x + row * DIM);
        #pragma unroll
        for (int j = 0; j < DIM / 4; j++) {
            float4 v = xin[j];
            r[4*j+0] = v.x; r[4*j+1] = v.y; r[4*j+2] = v.z; r[4*j+3] = v.w;
            xq[4*j+0] = 0.f; xq[4*j+1] = 0.f; xq[4*j+2] = 0.f; xq[4*j+3] = 0.f;
        }
    }

    int   best_idx[NLAYER];
    float loss_sum = 0.f;

    for (int l = 0; l < NLAYER; l++) {
        __syncthreads();  // protect smem reuse across layers
        // Stage layer-l codebook (coalesced float4)
        {
            const float4* gcb = (const float4*)(codebooks + (size_t)l * NE * DIM);
            float4* sc4 = (float4*)sc;
            #pragma unroll
            for (int i = tid; i < NE * DIM / 4; i += TPB) sc4[i] = gcb[i];
        }
        __syncthreads();
        for (int e = tid; e < NE; e += TPB) {
            const float* c = sc + e * DIM;
            float s = 0.f;
            #pragma unroll
            for (int d = 0; d < DIM; d++) s = fmaf(c[d], c[d], s);
            ccn[e] = s;
        }
        __syncthreads();

        // ||r||^2 and packed residual
        float rr = 0.f;
        #pragma unroll
        for (int d = 0; d < DIM; d++) rr = fmaf(r[d], r[d], rr);
        uint64_t r2[DIM / 2];
        #pragma unroll
        for (int k = 0; k < DIM / 2; k++) r2[k] = pack2(r[2*k], r[2*k+1]);

        // Argmin over 256 codes using packed f32x2 FMA (2 MACs/inst)
        float bd = 3.4e38f;
        int   be = 0;
        #pragma unroll 2
        for (int e = 0; e < NE; e++) {
            const ulonglong2* c2 = (const ulonglong2*)(sc + e * DIM); // broadcast LDS.128
            uint64_t acc0 = 0ull, acc1 = 0ull;
            #pragma unroll
            for (int j = 0; j < DIM / 4; j++) {
                ulonglong2 c = c2[j];
                fma2(acc0, r2[2*j + 0], c.x);
                fma2(acc1, r2[2*j + 1], c.y);
            }
            float s0, s1;
            unpack2(add2(acc0, acc1), s0, s1);
            float dot  = s0 + s1;
            float dist = fmaf(-2.f, dot, rr + ccn[e]);  // == (rr+ccn) - 2*dot exactly
            if (dist < bd) { bd = dist; be = e; }       // strict < == first-min
        }
        best_idx[l] = be;

        // Update: diff = c - r; loss += diff^2; xq += c; r = -(c - r)
        {
            const float4* cb = (const float4*)(sc + be * DIM);
            #pragma unroll
            for (int j = 0; j < DIM / 4; j++) {
                float4 c = cb[j];
                float d0 = c.x - r[4*j+0];
                float d1 = c.y - r[4*j+1];
                float d2 = c.z - r[4*j+2];
                float d3 = c.w - r[4*j+3];
                loss_sum = fmaf(d0, d0, loss_sum);
                loss_sum = fmaf(d1, d1, loss_sum);
                loss_sum = fmaf(d2, d2, loss_sum);
                loss_sum = fmaf(d3, d3, loss_sum);
                xq[4*j+0] += c.x; xq[4*j+1] += c.y;
                xq[4*j+2] += c.z; xq[4*j+3] += c.w;
                r[4*j+0] = -d0; r[4*j+1] = -d1;
                r[4*j+2] = -d2; r[4*j+3] = -d3;
            }
        }
    }

    // Write x_q (16B aligned)
    {
        float4* xo = (float4*)(out + row * DIM);
        #pragma unroll
        for (int j = 0; j < DIM / 4; j++)
            xo[j] = make_float4(xq[4*j+0], xq[4*j+1], xq[4*j+2], xq[4*j+3]);
    }
    // Indices as float, [N, L], region only 4B aligned -> scalar stores
    {
        float* oi = out + (size_t)N_ROWS * DIM + 1 + row * NLAYER;
        #pragma unroll
        for (int l = 0; l < NLAYER; l++) oi[l] = (float)best_idx[l];
    }

    // ---- loss: block reduce -> per-block partial -> last block finalizes ----
    __shared__ float warp_part[TPB / 32];
    #pragma unroll
    for (int off = 16; off > 0; off >>= 1)
        loss_sum += __shfl_down_sync(0xFFFFFFFFu, loss_sum, off);
    const int lane = tid & 31, wid = tid >> 5;
    if (lane == 0) warp_part[wid] = loss_sum;
    __syncthreads();

    __shared__ bool is_last;
    if (tid == 0) {
        float s = warp_part[0] + warp_part[1] + warp_part[2] + warp_part[3];
        g_part[blockIdx.x] = (double)s;
        __threadfence();
        unsigned t = atomicAdd(&g_count, 1u);
        is_last = (t == (unsigned)(gridDim.x - 1));
    }
    __syncthreads();

    if (is_last) {
        // Deterministic final reduction (fixed per-thread assignment + fixed tree)
        double acc = 0.0;
        for (int i = tid; i < NBLK; i += TPB) acc += g_part[i];
        double* dsm = (double*)smem;  // reuse dynamic smem
        dsm[tid] = acc;
        __syncthreads();
        #pragma unroll
        for (int s = TPB / 2; s > 0; s >>= 1) {
            if (tid < s) dsm[tid] += dsm[tid + s];
            __syncthreads();
        }
        if (tid == 0) {
            double scale = (1.0 + (double)BETA) /
                           ((double)NLAYER * (double)N_ROWS * (double)DIM);
            out[(size_t)N_ROWS * DIM] = (float)(dsm[0] * scale);
            g_count = 0;  // reset for next (graph-replayed) launch
        }
    }
}

extern "C" void kernel_launch(void* const* d_in, const int* in_sizes, int n_in,
                              void* d_out, int out_size)
{
    const float* x   = (const float*)d_in[0];
    const float* cbs = (const float*)d_in[1];
    float* out       = (float*)d_out;
    (void)in_sizes; (void)n_in; (void)out_size;

    const int smem = NE * DIM * sizeof(float) + NE * sizeof(float); // 33 KB
    rvq_main_kernel<<<NBLK, TPB, smem>>>(x, cbs, out);
}